// round 14
// baseline (speedup 1.0000x reference)
#include <cuda_runtime.h>
#include <cuda_fp16.h>
#include <cstdint>

// Problem constants
#define B_   8
#define C_   256
#define H_   64
#define W_   64
#define OC_  256
#define K_   9
#define HW_  4096
#define CK_  2304

// ---------------------------------------------------------------------------
// Device scratch (allocation-free rule)
// ---------------------------------------------------------------------------
__device__ __align__(256) __half g_colsT[(size_t)B_ * HW_ * CK_]; // 151 MB, [b][pix][k']
__device__ __align__(256) __half g_w[OC_ * CK_];                  // [oc][k'=k*256+c]
__device__ __align__(256) __half g_xth[(size_t)B_ * HW_ * C_];    // 67 MB, [b][pix][c]

// ---------------------------------------------------------------------------
// Helpers
// ---------------------------------------------------------------------------
__device__ __forceinline__ uint32_t smem_u32(const void* p) {
    uint32_t a;
    asm("{ .reg .u64 t; cvta.to.shared.u64 t, %1; cvt.u32.u64 %0, t; }"
        : "=r"(a) : "l"(p));
    return a;
}

__device__ __forceinline__ void cpasync16(uint32_t s, const void* g) {
    asm volatile("cp.async.cg.shared.global [%0], [%1], 16;" :: "r"(s), "l"(g));
}

__device__ __forceinline__ void ldsm_x4(uint32_t* r, uint32_t addr) {
    asm volatile("ldmatrix.sync.aligned.m8n8.x4.shared.b16 {%0,%1,%2,%3}, [%4];"
                 : "=r"(r[0]), "=r"(r[1]), "=r"(r[2]), "=r"(r[3]) : "r"(addr));
}

__device__ __forceinline__ void mma_f16(float* d, const uint32_t* a,
                                        uint32_t b0, uint32_t b1) {
    asm volatile(
        "mma.sync.aligned.m16n8k16.row.col.f32.f16.f16.f32 "
        "{%0,%1,%2,%3}, {%4,%5,%6,%7}, {%8,%9}, {%0,%1,%2,%3};"
        : "+f"(d[0]), "+f"(d[1]), "+f"(d[2]), "+f"(d[3])
        : "r"(a[0]), "r"(a[1]), "r"(a[2]), "r"(a[3]), "r"(b0), "r"(b1));
}

// ---------------------------------------------------------------------------
// Kernel 1: weight -> fp16, reorder K dim to k*256+c
// ---------------------------------------------------------------------------
__global__ void wsplit_kernel(const float* __restrict__ w) {
    int i = blockIdx.x * blockDim.x + threadIdx.x;
    if (i >= OC_ * CK_) return;
    int oc  = i / CK_;
    int rem = i % CK_;
    int c   = rem / K_;
    int k   = rem % K_;
    g_w[(size_t)oc * CK_ + k * C_ + c] = __float2half(w[i]);
}

// ---------------------------------------------------------------------------
// Kernel 2: transpose x (B,C,HW) fp32 -> g_xth (B,HW,C) fp16
// ---------------------------------------------------------------------------
__global__ void __launch_bounds__(256)
transpose_kernel(const float* __restrict__ x) {
    __shared__ float tile[32][33];
    int b  = blockIdx.z;
    int ct = blockIdx.y;
    int pt = blockIdx.x;
    int tx  = threadIdx.x & 31;
    int ty4 = (threadIdx.x >> 5) * 4;

    const float* xb = x + (((size_t)(b * C_ + ct * 32)) << 12) + pt * 32;
#pragma unroll
    for (int i = 0; i < 4; i++)
        tile[ty4 + i][tx] = xb[((size_t)(ty4 + i) << 12) + tx];
    __syncthreads();
    __half* xtb = g_xth + ((size_t)(b * HW_) + pt * 32) * C_ + ct * 32;
#pragma unroll
    for (int i = 0; i < 4; i++)
        xtb[(size_t)(ty4 + i) * C_ + tx] = __float2half(tile[tx][ty4 + i]);
}

// ---------------------------------------------------------------------------
// Kernel 3: im2col DIRECT — warp = one pixel, lane = 8 channels.
// Writes cols_t[b][pix][k*256+c] straight from registers: one coalesced
// 512B STG per (pixel, tap). No smem, no barriers.
// ---------------------------------------------------------------------------
__global__ void __launch_bounds__(256, 8)
im2col_kernel(const float* __restrict__ offset, const float* __restrict__ mask) {
    int b    = blockIdx.y;
    int tid  = threadIdx.x;
    int wid  = tid >> 5;
    int lid  = tid & 31;
    int pixg = blockIdx.x * 8 + wid;

    const __half* xbh = g_xth + ((size_t)b * HW_) * C_;
    __half* dstRow = g_colsT + ((size_t)(b * HW_) + pixg) * CK_;
    int ho = pixg >> 6, wo = pixg & 63;
    int co = lid * 8;

#pragma unroll
    for (int k = 0; k < K_; k++) {
        // sampling prep (uniform across warp; broadcast loads)
        float dy = __ldg(&offset[((size_t)(b * 18 + 2 * k) << 12) + pixg]);
        float dx = __ldg(&offset[((size_t)(b * 18 + 2 * k + 1) << 12) + pixg]);
        float m  = __ldg(&mask[((size_t)(b * 9 + k) << 12) + pixg]);
        float py = (float)(k / 3) + (float)(ho - 1) + dy;
        float px = (float)(k % 3) + (float)(wo - 1) + dx;
        float y0f = floorf(py), x0f = floorf(px);
        float wy1 = py - y0f, wx1 = px - x0f;
        float wy0 = 1.0f - wy1, wx0 = 1.0f - wx1;
        int y0 = (int)y0f, x0 = (int)x0f;
        int y1 = y0 + 1, x1 = x0 + 1;
        float v00 = (y0 >= 0 && y0 < H_ && x0 >= 0 && x0 < W_) ? 1.0f : 0.0f;
        float v01 = (y0 >= 0 && y0 < H_ && x1 >= 0 && x1 < W_) ? 1.0f : 0.0f;
        float v10 = (y1 >= 0 && y1 < H_ && x0 >= 0 && x0 < W_) ? 1.0f : 0.0f;
        float v11 = (y1 >= 0 && y1 < H_ && x1 >= 0 && x1 < W_) ? 1.0f : 0.0f;
        int yi0 = min(max(y0, 0), H_ - 1), yi1 = min(max(y1, 0), H_ - 1);
        int xi0 = min(max(x0, 0), W_ - 1), xi1 = min(max(x1, 0), W_ - 1);
        float4 wv = make_float4(wy0 * wx0 * v00 * m, wy0 * wx1 * v01 * m,
                                wy1 * wx0 * v10 * m, wy1 * wx1 * v11 * m);
        int4 si = make_int4(yi0 * W_ + xi0, yi0 * W_ + xi1,
                            yi1 * W_ + xi0, yi1 * W_ + xi1);

        float acc[8];
#pragma unroll
        for (int j = 0; j < 8; j++) acc[j] = 0.0f;

#define CORNER(IDX, WW)                                                        \
        {                                                                      \
            uint4 u = *(const uint4*)(xbh + ((size_t)(IDX) << 8) + co);        \
            const __half2* hp = (const __half2*)&u;                            \
            _Pragma("unroll")                                                  \
            for (int j = 0; j < 4; j++) {                                      \
                float2 f = __half22float2(hp[j]);                              \
                acc[2 * j]     += (WW) * f.x;                                  \
                acc[2 * j + 1] += (WW) * f.y;                                  \
            }                                                                  \
        }
        CORNER(si.x, wv.x)
        CORNER(si.y, wv.y)
        CORNER(si.z, wv.z)
        CORNER(si.w, wv.w)
#undef CORNER

        uint4 o;
        __half2* op = (__half2*)&o;
#pragma unroll
        for (int j = 0; j < 4; j++)
            op[j] = __floats2half2_rn(acc[2 * j], acc[2 * j + 1]);
        *(uint4*)(dstRow + k * C_ + co) = o;
    }
}

// ---------------------------------------------------------------------------
// Kernel 4: fp16 HMMA GEMM — BK=64, 3-stage pipeline, compile-time stages,
// one sync per K-iter. B now n-major (cols_t rows), non-trans ldmatrix.
// CTA 128x128, 8 warps (2Mx4N), warp tile 64x32.
// ---------------------------------------------------------------------------
#define BKG    64
#define NKIT   (CK_ / BKG)          // 36 (= 12 * 3)
#define AROW   72                   // 64 + 8 pad (halves)
#define BROW   72                   // 64 + 8 pad (halves) — B rows are k-extent
#define A_STG  (128 * AROW * 2)     // 18432 B per stage
#define B_STG  (128 * BROW * 2)     // 18432 B per stage (128 pix rows)
#define SMEM_BYTES (3 * (A_STG + B_STG))   // 110592 B

__device__ __forceinline__ void compute_chunk(uint32_t sA, uint32_t sB,
                                              float acc[4][4][4]) {
#pragma unroll
    for (int ks = 0; ks < 4; ks++) {
        uint32_t a[4][4];
#pragma unroll
        for (int mt = 0; mt < 4; mt++)
            ldsm_x4(a[mt], sA + mt * (16 * AROW * 2) + ks * 32);
        // B fragments, n-major, non-trans: matrices [n0-7 k0-7][n8-15 k0-7]
        // [n0-7 k8-15][n8-15 k8-15] -> b0=bf[nt&1], b1=bf[(nt&1)+2]
        uint32_t bf[2][4];
#pragma unroll
        for (int pr = 0; pr < 2; pr++)
            ldsm_x4(bf[pr], sB + pr * (16 * BROW * 2) + ks * 32);
#pragma unroll
        for (int mt = 0; mt < 4; mt++)
#pragma unroll
            for (int nt = 0; nt < 4; nt++)
                mma_f16(acc[mt][nt], a[mt],
                        bf[nt >> 1][nt & 1], bf[nt >> 1][(nt & 1) + 2]);
    }
}

__global__ void __launch_bounds__(256, 2)
gemm_mma_kernel(const float* __restrict__ bias, float* __restrict__ out) {
    extern __shared__ __align__(16) __half sm[];

    const int tid   = threadIdx.x;
    const int wid   = tid >> 5;
    const int lid   = tid & 31;
    const int wm    = wid >> 2;
    const int wn    = wid & 3;
    const int nBase = blockIdx.x * 128;
    const int mBase = blockIdx.y * 128;
    const int b     = blockIdx.z;

    const uint32_t smA = smem_u32(sm);
    const uint32_t smB = smA + 3 * A_STG;

    // ---- hoisted cp.async addresses ----
    // A: 128 rows x 128B -> 4 chunks/thread
    uint32_t stA[4];
    const __half* gA[4];
#pragma unroll
    for (int j = 0; j < 4; j++) {
        int piece = tid + j * 256;
        int row = piece >> 3, seg = piece & 7;
        stA[j] = smA + (row * AROW + seg * 8) * 2;
        gA[j]  = g_w + (size_t)(mBase + row) * CK_ + seg * 8;
    }
    // B: 128 pixel-rows x 128B -> 4 chunks/thread; kt advances within row
    uint32_t stB[4];
    const __half* gB[4];
#pragma unroll
    for (int j = 0; j < 4; j++) {
        int piece = tid + j * 256;
        int row = piece >> 3, seg = piece & 7;
        stB[j] = smB + (row * BROW + seg * 8) * 2;
        gB[j]  = g_colsT + ((size_t)(b * HW_ + nBase + row)) * CK_ + seg * 8;
    }

    // ---- hoisted ldsm read addresses ----
    const uint32_t aRd = smA + ((wm * 64 + (lid & 15)) * AROW
                                + ((lid >> 4) & 1) * 8) * 2;
    const uint32_t bRd = smB + ((wn * 32 + (lid & 15)) * BROW
                                + ((lid >> 4) & 1) * 8) * 2;

    float acc[4][4][4];
#pragma unroll
    for (int i = 0; i < 4; i++)
#pragma unroll
        for (int j = 0; j < 4; j++)
#pragma unroll
            for (int q = 0; q < 4; q++) acc[i][j][q] = 0.0f;

    auto load_stage = [&](uint32_t oA, uint32_t oB, int kt) {
#pragma unroll
        for (int j = 0; j < 4; j++)
            cpasync16(stA[j] + oA, gA[j] + kt);
#pragma unroll
        for (int j = 0; j < 4; j++)
            cpasync16(stB[j] + oB, gB[j] + kt);
        asm volatile("cp.async.commit_group;" ::: "memory");
    };

    load_stage(0, 0, 0);
    load_stage(A_STG, B_STG, BKG);

#define GBODY(S, IDX)                                                          \
    {                                                                          \
        if ((IDX) == NKIT - 1)                                                 \
            asm volatile("cp.async.wait_group 0;" ::: "memory");               \
        else                                                                   \
            asm volatile("cp.async.wait_group 1;" ::: "memory");               \
        __syncthreads();                                                       \
        int nk = (IDX) + 2;                                                    \
        if (nk < NKIT)                                                         \
            load_stage((((S) + 2) % 3) * A_STG, (((S) + 2) % 3) * B_STG,       \
                       nk * BKG);                                              \
        compute_chunk(aRd + (S) * A_STG, bRd + (S) * B_STG, acc);              \
    }

    for (int i = 0; i < NKIT; i += 3) {
        GBODY(0, i)
        GBODY(1, i + 1)
        GBODY(2, i + 2)
    }
#undef GBODY

    // Epilogue
    const int r  = lid >> 2;
    const int cc = (lid & 3) * 2;
#pragma unroll
    for (int mt = 0; mt < 4; mt++) {
        int oc0 = mBase + wm * 64 + mt * 16 + r;
        float bz0 = bias[oc0];
        float bz1 = bias[oc0 + 8];
        float* o0 = out + (((size_t)(b * OC_ + oc0)) << 12) + nBase;
        float* o1 = out + (((size_t)(b * OC_ + oc0 + 8)) << 12) + nBase;
#pragma unroll
        for (int nt = 0; nt < 4; nt++) {
            int px = wn * 32 + nt * 8 + cc;
            float2 v0 = make_float2(acc[mt][nt][0] + bz0, acc[mt][nt][1] + bz0);
            float2 v1 = make_float2(acc[mt][nt][2] + bz1, acc[mt][nt][3] + bz1);
            *(float2*)(o0 + px) = v0;
            *(float2*)(o1 + px) = v1;
        }
    }
}

// ---------------------------------------------------------------------------
extern "C" void kernel_launch(void* const* d_in, const int* in_sizes, int n_in,
                              void* d_out, int out_size) {
    const float* x      = (const float*)d_in[0];
    const float* offset = (const float*)d_in[1];
    const float* mask   = (const float*)d_in[2];
    const float* weight = (const float*)d_in[3];
    const float* bias   = (const float*)d_in[4];
    float* out          = (float*)d_out;

    wsplit_kernel<<<(OC_ * CK_ + 255) / 256, 256>>>(weight);
    {
        dim3 grid(128, 8, 8);
        transpose_kernel<<<grid, 256>>>(x);
    }
    {
        dim3 grid(HW_ / 8, B_);
        im2col_kernel<<<grid, 256>>>(offset, mask);
    }
    {
        static bool attrSet = false;
        if (!attrSet) {
            cudaFuncSetAttribute(gemm_mma_kernel,
                                 cudaFuncAttributeMaxDynamicSharedMemorySize,
                                 SMEM_BYTES);
            attrSet = true;
        }
        dim3 grid(HW_ / 128, OC_ / 128, B_);
        gemm_mma_kernel<<<grid, 256, SMEM_BYTES>>>(bias, out);
    }
}

// round 15
// speedup vs baseline: 1.0865x; 1.0865x over previous
#include <cuda_runtime.h>
#include <cuda_fp16.h>
#include <cstdint>

// Problem constants
#define B_   8
#define C_   256
#define H_   64
#define W_   64
#define OC_  256
#define K_   9
#define HW_  4096
#define CK_  2304

// ---------------------------------------------------------------------------
// Device scratch (allocation-free rule)
// ---------------------------------------------------------------------------
__device__ __align__(256) __half g_colsT[(size_t)B_ * HW_ * CK_]; // 151 MB, [b][pix][k']
__device__ __align__(256) __half g_w[OC_ * CK_];                  // [oc][k'=k*256+c]
__device__ __align__(256) __half g_xth[(size_t)B_ * HW_ * C_];    // 67 MB, [b][pix][c]

// ---------------------------------------------------------------------------
// Helpers
// ---------------------------------------------------------------------------
__device__ __forceinline__ uint32_t smem_u32(const void* p) {
    uint32_t a;
    asm("{ .reg .u64 t; cvta.to.shared.u64 t, %1; cvt.u32.u64 %0, t; }"
        : "=r"(a) : "l"(p));
    return a;
}

__device__ __forceinline__ void cpasync16(uint32_t s, const void* g) {
    asm volatile("cp.async.cg.shared.global [%0], [%1], 16;" :: "r"(s), "l"(g));
}

__device__ __forceinline__ void ldsm_x4(uint32_t* r, uint32_t addr) {
    asm volatile("ldmatrix.sync.aligned.m8n8.x4.shared.b16 {%0,%1,%2,%3}, [%4];"
                 : "=r"(r[0]), "=r"(r[1]), "=r"(r[2]), "=r"(r[3]) : "r"(addr));
}

__device__ __forceinline__ void mma_f16(float* d, const uint32_t* a,
                                        uint32_t b0, uint32_t b1) {
    asm volatile(
        "mma.sync.aligned.m16n8k16.row.col.f32.f16.f16.f32 "
        "{%0,%1,%2,%3}, {%4,%5,%6,%7}, {%8,%9}, {%0,%1,%2,%3};"
        : "+f"(d[0]), "+f"(d[1]), "+f"(d[2]), "+f"(d[3])
        : "r"(a[0]), "r"(a[1]), "r"(a[2]), "r"(a[3]), "r"(b0), "r"(b1));
}

// ---------------------------------------------------------------------------
// Kernel 1: weight -> fp16, reorder K dim to k*256+c
// ---------------------------------------------------------------------------
__global__ void wsplit_kernel(const float* __restrict__ w) {
    int i = blockIdx.x * blockDim.x + threadIdx.x;
    if (i >= OC_ * CK_) return;
    int oc  = i / CK_;
    int rem = i % CK_;
    int c   = rem / K_;
    int k   = rem % K_;
    g_w[(size_t)oc * CK_ + k * C_ + c] = __float2half(w[i]);
}

// ---------------------------------------------------------------------------
// Kernel 2: transpose x (B,C,HW) fp32 -> g_xth (B,HW,C) fp16
// ---------------------------------------------------------------------------
__global__ void __launch_bounds__(256)
transpose_kernel(const float* __restrict__ x) {
    __shared__ float tile[32][33];
    int b  = blockIdx.z;
    int ct = blockIdx.y;
    int pt = blockIdx.x;
    int tx  = threadIdx.x & 31;
    int ty4 = (threadIdx.x >> 5) * 4;

    const float* xb = x + (((size_t)(b * C_ + ct * 32)) << 12) + pt * 32;
#pragma unroll
    for (int i = 0; i < 4; i++)
        tile[ty4 + i][tx] = xb[((size_t)(ty4 + i) << 12) + tx];
    __syncthreads();
    __half* xtb = g_xth + ((size_t)(b * HW_) + pt * 32) * C_ + ct * 32;
#pragma unroll
    for (int i = 0; i < 4; i++)
        xtb[(size_t)(ty4 + i) * C_ + tx] = __float2half(tile[tx][ty4 + i]);
}

// ---------------------------------------------------------------------------
// Kernel 3: im2col DIRECT — warp = one pixel, lane = 8 channels.
// Writes cols_t[b][pix][k*256+c] straight from registers: one coalesced
// 512B STG per (pixel, tap). No smem, no barriers.
// ---------------------------------------------------------------------------
__global__ void __launch_bounds__(256, 8)
im2col_kernel(const float* __restrict__ offset, const float* __restrict__ mask) {
    int b    = blockIdx.y;
    int tid  = threadIdx.x;
    int wid  = tid >> 5;
    int lid  = tid & 31;
    int pixg = blockIdx.x * 8 + wid;

    const __half* xbh = g_xth + ((size_t)b * HW_) * C_;
    __half* dstRow = g_colsT + ((size_t)(b * HW_) + pixg) * CK_;
    int ho = pixg >> 6, wo = pixg & 63;
    int co = lid * 8;

#pragma unroll
    for (int k = 0; k < K_; k++) {
        // sampling prep (uniform across warp; broadcast loads)
        float dy = __ldg(&offset[((size_t)(b * 18 + 2 * k) << 12) + pixg]);
        float dx = __ldg(&offset[((size_t)(b * 18 + 2 * k + 1) << 12) + pixg]);
        float m  = __ldg(&mask[((size_t)(b * 9 + k) << 12) + pixg]);
        float py = (float)(k / 3) + (float)(ho - 1) + dy;
        float px = (float)(k % 3) + (float)(wo - 1) + dx;
        float y0f = floorf(py), x0f = floorf(px);
        float wy1 = py - y0f, wx1 = px - x0f;
        float wy0 = 1.0f - wy1, wx0 = 1.0f - wx1;
        int y0 = (int)y0f, x0 = (int)x0f;
        int y1 = y0 + 1, x1 = x0 + 1;
        float v00 = (y0 >= 0 && y0 < H_ && x0 >= 0 && x0 < W_) ? 1.0f : 0.0f;
        float v01 = (y0 >= 0 && y0 < H_ && x1 >= 0 && x1 < W_) ? 1.0f : 0.0f;
        float v10 = (y1 >= 0 && y1 < H_ && x0 >= 0 && x0 < W_) ? 1.0f : 0.0f;
        float v11 = (y1 >= 0 && y1 < H_ && x1 >= 0 && x1 < W_) ? 1.0f : 0.0f;
        int yi0 = min(max(y0, 0), H_ - 1), yi1 = min(max(y1, 0), H_ - 1);
        int xi0 = min(max(x0, 0), W_ - 1), xi1 = min(max(x1, 0), W_ - 1);
        float4 wv = make_float4(wy0 * wx0 * v00 * m, wy0 * wx1 * v01 * m,
                                wy1 * wx0 * v10 * m, wy1 * wx1 * v11 * m);
        int4 si = make_int4(yi0 * W_ + xi0, yi0 * W_ + xi1,
                            yi1 * W_ + xi0, yi1 * W_ + xi1);

        float acc[8];
#pragma unroll
        for (int j = 0; j < 8; j++) acc[j] = 0.0f;

#define CORNER(IDX, WW)                                                        \
        {                                                                      \
            uint4 u = *(const uint4*)(xbh + ((size_t)(IDX) << 8) + co);        \
            const __half2* hp = (const __half2*)&u;                            \
            _Pragma("unroll")                                                  \
            for (int j = 0; j < 4; j++) {                                      \
                float2 f = __half22float2(hp[j]);                              \
                acc[2 * j]     += (WW) * f.x;                                  \
                acc[2 * j + 1] += (WW) * f.y;                                  \
            }                                                                  \
        }
        CORNER(si.x, wv.x)
        CORNER(si.y, wv.y)
        CORNER(si.z, wv.z)
        CORNER(si.w, wv.w)
#undef CORNER

        uint4 o;
        __half2* op = (__half2*)&o;
#pragma unroll
        for (int j = 0; j < 4; j++)
            op[j] = __floats2half2_rn(acc[2 * j], acc[2 * j + 1]);
        *(uint4*)(dstRow + k * C_ + co) = o;
    }
}

// ---------------------------------------------------------------------------
// Kernel 4: fp16 HMMA GEMM — BK=64, 3-stage pipeline, compile-time stages,
// one sync per K-iter. B n-major (cols_t rows), non-trans ldmatrix with
// lane mapping chosen so each mma consumes ADJACENT B registers (r0,r1):
// matrices = (n0-7,k0)(n0-7,k8)(n8-15,k0)(n8-15,k8).
// CTA 128x128, 8 warps (2Mx4N), warp tile 64x32.
// ---------------------------------------------------------------------------
#define BKG    64
#define NKIT   (CK_ / BKG)          // 36 (= 12 * 3)
#define AROW   72                   // 64 + 8 pad (halves)
#define BROW   72                   // 64 + 8 pad (halves)
#define A_STG  (128 * AROW * 2)     // 18432 B per stage
#define B_STG  (128 * BROW * 2)     // 18432 B per stage (128 pix rows)
#define SMEM_BYTES (3 * (A_STG + B_STG))   // 110592 B

__device__ __forceinline__ void compute_chunk(uint32_t sA, uint32_t sB,
                                              float acc[4][4][4]) {
#pragma unroll
    for (int ks = 0; ks < 4; ks++) {
        uint32_t a[4][4];
#pragma unroll
        for (int mt = 0; mt < 4; mt++)
            ldsm_x4(a[mt], sA + mt * (16 * AROW * 2) + ks * 32);
        // B fragments: bf[pr] covers n-range pr*16..+15 with matrices
        // (n0-7,k0)(n0-7,k8)(n8-15,k0)(n8-15,k8) -> adjacent reg pairs.
        uint32_t bf[2][4];
#pragma unroll
        for (int pr = 0; pr < 2; pr++)
            ldsm_x4(bf[pr], sB + pr * (16 * BROW * 2) + ks * 32);
#pragma unroll
        for (int mt = 0; mt < 4; mt++)
#pragma unroll
            for (int nt = 0; nt < 4; nt++)
                mma_f16(acc[mt][nt], a[mt],
                        bf[nt >> 1][(nt & 1) * 2], bf[nt >> 1][(nt & 1) * 2 + 1]);
    }
}

__global__ void __launch_bounds__(256, 2)
gemm_mma_kernel(const float* __restrict__ bias, float* __restrict__ out) {
    extern __shared__ __align__(16) __half sm[];

    const int tid   = threadIdx.x;
    const int wid   = tid >> 5;
    const int lid   = tid & 31;
    const int wm    = wid >> 2;
    const int wn    = wid & 3;
    const int nBase = blockIdx.x * 128;
    const int mBase = blockIdx.y * 128;
    const int b     = blockIdx.z;

    const uint32_t smA = smem_u32(sm);
    const uint32_t smB = smA + 3 * A_STG;

    // ---- hoisted cp.async addresses ----
    // A: 128 rows x 128B -> 4 chunks/thread
    uint32_t stA[4];
    const __half* gA[4];
#pragma unroll
    for (int j = 0; j < 4; j++) {
        int piece = tid + j * 256;
        int row = piece >> 3, seg = piece & 7;
        stA[j] = smA + (row * AROW + seg * 8) * 2;
        gA[j]  = g_w + (size_t)(mBase + row) * CK_ + seg * 8;
    }
    // B: 128 pixel-rows x 128B -> 4 chunks/thread; kt advances within row
    uint32_t stB[4];
    const __half* gB[4];
#pragma unroll
    for (int j = 0; j < 4; j++) {
        int piece = tid + j * 256;
        int row = piece >> 3, seg = piece & 7;
        stB[j] = smB + (row * BROW + seg * 8) * 2;
        gB[j]  = g_colsT + ((size_t)(b * HW_ + nBase + row)) * CK_ + seg * 8;
    }

    // ---- hoisted ldsm read addresses ----
    const uint32_t aRd = smA + ((wm * 64 + (lid & 15)) * AROW
                                + ((lid >> 4) & 1) * 8) * 2;
    // B lane mapping: row = wn*32 + ((lid>>4)&1)*8 + (lid&7), k-half = (lid>>3)&1
    const uint32_t bRd = smB + ((wn * 32 + ((lid >> 4) & 1) * 8 + (lid & 7)) * BROW
                                + ((lid >> 3) & 1) * 8) * 2;

    float acc[4][4][4];
#pragma unroll
    for (int i = 0; i < 4; i++)
#pragma unroll
        for (int j = 0; j < 4; j++)
#pragma unroll
            for (int q = 0; q < 4; q++) acc[i][j][q] = 0.0f;

    auto load_stage = [&](uint32_t oA, uint32_t oB, int kt) {
#pragma unroll
        for (int j = 0; j < 4; j++)
            cpasync16(stA[j] + oA, gA[j] + kt);
#pragma unroll
        for (int j = 0; j < 4; j++)
            cpasync16(stB[j] + oB, gB[j] + kt);
        asm volatile("cp.async.commit_group;" ::: "memory");
    };

    load_stage(0, 0, 0);
    load_stage(A_STG, B_STG, BKG);

#define GBODY(S, IDX)                                                          \
    {                                                                          \
        if ((IDX) == NKIT - 1)                                                 \
            asm volatile("cp.async.wait_group 0;" ::: "memory");               \
        else                                                                   \
            asm volatile("cp.async.wait_group 1;" ::: "memory");               \
        __syncthreads();                                                       \
        int nk = (IDX) + 2;                                                    \
        if (nk < NKIT)                                                         \
            load_stage((((S) + 2) % 3) * A_STG, (((S) + 2) % 3) * B_STG,       \
                       nk * BKG);                                              \
        compute_chunk(aRd + (S) * A_STG, bRd + (S) * B_STG, acc);              \
    }

    for (int i = 0; i < NKIT; i += 3) {
        GBODY(0, i)
        GBODY(1, i + 1)
        GBODY(2, i + 2)
    }
#undef GBODY

    // Epilogue
    const int r  = lid >> 2;
    const int cc = (lid & 3) * 2;
#pragma unroll
    for (int mt = 0; mt < 4; mt++) {
        int oc0 = mBase + wm * 64 + mt * 16 + r;
        float bz0 = bias[oc0];
        float bz1 = bias[oc0 + 8];
        float* o0 = out + (((size_t)(b * OC_ + oc0)) << 12) + nBase;
        float* o1 = out + (((size_t)(b * OC_ + oc0 + 8)) << 12) + nBase;
#pragma unroll
        for (int nt = 0; nt < 4; nt++) {
            int px = wn * 32 + nt * 8 + cc;
            float2 v0 = make_float2(acc[mt][nt][0] + bz0, acc[mt][nt][1] + bz0);
            float2 v1 = make_float2(acc[mt][nt][2] + bz1, acc[mt][nt][3] + bz1);
            *(float2*)(o0 + px) = v0;
            *(float2*)(o1 + px) = v1;
        }
    }
}

// ---------------------------------------------------------------------------
extern "C" void kernel_launch(void* const* d_in, const int* in_sizes, int n_in,
                              void* d_out, int out_size) {
    const float* x      = (const float*)d_in[0];
    const float* offset = (const float*)d_in[1];
    const float* mask   = (const float*)d_in[2];
    const float* weight = (const float*)d_in[3];
    const float* bias   = (const float*)d_in[4];
    float* out          = (float*)d_out;

    wsplit_kernel<<<(OC_ * CK_ + 255) / 256, 256>>>(weight);
    {
        dim3 grid(128, 8, 8);
        transpose_kernel<<<grid, 256>>>(x);
    }
    {
        dim3 grid(HW_ / 8, B_);
        im2col_kernel<<<grid, 256>>>(offset, mask);
    }
    {
        static bool attrSet = false;
        if (!attrSet) {
            cudaFuncSetAttribute(gemm_mma_kernel,
                                 cudaFuncAttributeMaxDynamicSharedMemorySize,
                                 SMEM_BYTES);
            attrSet = true;
        }
        dim3 grid(HW_ / 128, OC_ / 128, B_);
        gemm_mma_kernel<<<grid, 256, SMEM_BYTES>>>(bias, out);
    }
}